// round 16
// baseline (speedup 1.0000x reference)
#include <cuda_runtime.h>
#include <cuda_bf16.h>
#include <math.h>
#include <stdint.h>

#define BSZ   32
#define TLEN  64
#define ED    512
#define HD    512
#define G4    2048
#define M2    2048
#define VOC   32000
#define RB    128
#define NHELP 20
#define NGW   16          // group-worker helpers

// ---------------- scratch (device globals; no allocation) ----------------
__device__ float    g_preE[M2 * G4];
__device__ float    g_preD[M2 * G4];
__device__ uint16_t g_xsh[M2 * ED];                     // enc inputs (hi)
__device__ uint16_t g_xsd[M2 * ED];                     // dec inputs (hi)
__device__ uint16_t g_wh [G4 * ED], g_wl [G4 * ED];     // e0_Wih planes
__device__ uint16_t g_wh2[G4 * ED], g_wl2[G4 * ED];     // d0_Wih planes
__device__ uint16_t g_lwh[VOC * ED], g_lwl[VOC * ED];   // lin_W planes
__device__ uint16_t g_u2h[M2 * HD];
__device__ uint32_t g_hq[2][2][2][8192];
__device__ __align__(16) unsigned g_flags2[RB * 32];
__device__ unsigned g_epoch;        // launch counter (bumped by front kernel)
__device__ unsigned g_gdone[64];    // per-group arrival counters (monotonic)
__device__ unsigned g_prog;         // input-GEMM progress (monotonic, +64/launch)
__device__ unsigned g_lq;           // lin-pack ticket queue (monotonic)

// ================= helpers =================
__device__ __forceinline__ uint32_t smem_u32(const void* p) {
    uint32_t a;
    asm("{ .reg .u64 t; cvta.to.shared.u64 t, %1; cvt.u32.u64 %0, t; }" : "=r"(a) : "l"(p));
    return a;
}
__device__ __forceinline__ float fsig(float x) {
    return __fdividef(1.f, 1.f + __expf(-x));
}
__device__ __forceinline__ float ftanh(float x) {
    return 1.f - __fdividef(2.f, __expf(2.f * x) + 1.f);
}

#define LDMX4(r0, r1, r2, r3, a) \
    asm volatile("ldmatrix.sync.aligned.m8n8.x4.shared.b16 {%0,%1,%2,%3}, [%4];" \
        : "=r"(r0), "=r"(r1), "=r"(r2), "=r"(r3) : "r"(a))

#define LDMX4T(r0, r1, r2, r3, a) \
    asm volatile("ldmatrix.sync.aligned.m8n8.x4.trans.shared.b16 {%0,%1,%2,%3}, [%4];" \
        : "=r"(r0), "=r"(r1), "=r"(r2), "=r"(r3) : "r"(a))

#define STS128(a, r0, r1, r2, r3) \
    asm volatile("st.shared.v4.b32 [%0], {%1,%2,%3,%4};" \
        :: "r"(a), "r"(r0), "r"(r1), "r"(r2), "r"(r3) : "memory")

__device__ __forceinline__ void mma16816(float* d, const uint32_t* a, const uint32_t* b) {
    asm volatile("mma.sync.aligned.m16n8k16.row.col.f32.bf16.bf16.f32 "
        "{%0,%1,%2,%3},{%4,%5,%6,%7},{%8,%9},{%0,%1,%2,%3};"
        : "+f"(d[0]), "+f"(d[1]), "+f"(d[2]), "+f"(d[3])
        : "r"(a[0]), "r"(a[1]), "r"(a[2]), "r"(a[3]), "r"(b[0]), "r"(b[1]));
}

__device__ __forceinline__ void cvt2(float x, float y, uint32_t& hi, uint32_t& lo) {
    asm("cvt.rn.bf16x2.f32 %0, %1, %2;" : "=r"(hi) : "f"(y), "f"(x));
    float rx = x - __uint_as_float(hi << 16);
    float ry = y - __uint_as_float(hi & 0xFFFF0000u);
    asm("cvt.rn.bf16x2.f32 %0, %1, %2;" : "=r"(lo) : "f"(ry), "f"(rx));
}

// ================= fused front kernel =================
// blocks [0,64): zero g_hq; [64,1088): enc embed; [1088,2112): dec embed;
// [2112,2624): pack e0_Wih; [2624,3136): pack d0_Wih. Block 0 bumps g_epoch.
__global__ void k_front(const int* __restrict__ x, const int* __restrict__ tgt,
                        const float* __restrict__ enc_emb,
                        const float* __restrict__ dec_emb,
                        const float* __restrict__ e0_Wih,
                        const float* __restrict__ d0_Wih) {
    int b = blockIdx.x, tid = threadIdx.x;
    if (b == 0 && tid == 0) atomicAdd(&g_epoch, 1u);
    if (b < 64) {
        ((uint4*)g_hq)[b * 256 + tid] = make_uint4(0u, 0u, 0u, 0u);
    } else if (b < 2112) {
        int dec = (b >= 1088);
        int row = ((dec ? b - 1088 : b - 64) << 1) + (tid >> 7);
        int t = row >> 5, bb = row & 31;
        int tok = dec ? ((t == 0) ? 1 : tgt[bb * TLEN + t - 1]) : x[bb * TLEN + t];
        const float* emb = dec ? dec_emb : enc_emb;
        int c = tid & 127;
        float4 f = ((const float4*)(emb + (size_t)tok * ED))[c];
        uint32_t h0, l0, h1, l1;
        cvt2(f.x, f.y, h0, l0);
        cvt2(f.z, f.w, h1, l1);
        uint16_t* dst = dec ? g_xsd : g_xsh;
        *(uint2*)(dst + (size_t)row * ED + c * 4) = make_uint2(h0, h1);
    } else {
        int dec = (b >= 2624);
        size_t base = ((size_t)(dec ? b - 2624 : b - 2112) * 256 + tid) * 8;
        const float* src = dec ? d0_Wih : e0_Wih;
        uint16_t* hi = dec ? g_wh2 : g_wh;
        uint16_t* lo = dec ? g_wl2 : g_wl;
        float4 a = *(const float4*)(src + base);
        float4 c4 = *(const float4*)(src + base + 4);
        uint32_t h[4], l[4];
        cvt2(a.x, a.y, h[0], l[0]); cvt2(a.z, a.w, h[1], l[1]);
        cvt2(c4.x, c4.y, h[2], l[2]); cvt2(c4.z, c4.w, h[3], l[3]);
        *(uint4*)(hi + base) = make_uint4(h[0], h[1], h[2], h[3]);
        *(uint4*)(lo + base) = make_uint4(l[0], l[1], l[2], l[3]);
    }
}

// ====== 2-term split-bf16 HMMA GEMM, 128x256 tile (projection) ===========
#define QSTAGE 51200
#define QSMEM  102400

template<int PERM>
__global__ void __launch_bounds__(256, 1)
k_gemm_q(const uint16_t* __restrict__ Ah,
         const uint16_t* __restrict__ Bh, const uint16_t* __restrict__ Bl,
         const float* __restrict__ bias, float* __restrict__ C, int ldc) {
    extern __shared__ char smx[];
    uint32_t sb = smem_u32(smx);
    int tid = threadIdx.x, lid = tid & 31, wid = tid >> 5;
    int wm = wid >> 2, wn = wid & 3;
    int rb = blockIdx.x * 128, cb = blockIdx.y * 256;

    const uint8_t* srcp[10];
    uint32_t dstb[10];
    {
        const uint8_t* planes[3] = {(const uint8_t*)Ah, (const uint8_t*)Bh,
                                    (const uint8_t*)Bl};
        const uint32_t poff[3] = {0u, 10240u, 30720u};
        #pragma unroll
        for (int i = 0; i < 10; i++) {
            int s = i * 256 + tid;
            int isB = (s >= 512);
            int pl  = isB ? (1 + ((s - 512) >> 10)) : 0;
            int loc = isB ? ((s - 512) & 1023) : s;
            int row = loc >> 2, col = loc & 3;
            srcp[i] = planes[pl] + (size_t)((pl ? cb : rb) + row) * 1024 + col * 16;
            dstb[i] = sb + poff[pl] + (uint32_t)row * 80 + col * 16;
        }
    }

    uint4 v[10];
    #pragma unroll
    for (int i = 0; i < 10; i++) v[i] = *(const uint4*)(srcp[i]);
    #pragma unroll
    for (int i = 0; i < 10; i++) STS128(dstb[i], v[i].x, v[i].y, v[i].z, v[i].w);
    __syncthreads();

    uint32_t abase = sb + (uint32_t)(wm * 64 + (lid & 15)) * 80 + (lid >> 4) * 16;
    uint32_t bbase = sb + 10240 + (uint32_t)(wn * 64 + (lid & 15)) * 80 + (lid >> 4) * 16;

    float acc[4][8][4] = {};

    for (int c = 0; c < 16; c++) {
        if (c < 15) {
            #pragma unroll
            for (int i = 0; i < 10; i++) v[i] = *(const uint4*)(srcp[i] + (c + 1) * 64);
        }
        uint32_t so = (uint32_t)(c & 1) * QSTAGE;
        #pragma unroll
        for (int ks = 0; ks < 2; ks++) {
            uint32_t ah[4][4], bh[8][2], bl[8][2];
            #pragma unroll
            for (int sub = 0; sub < 4; sub++) {
                uint32_t ad = abase + so + (uint32_t)(sub * 16 * 80 + ks * 32);
                LDMX4(ah[sub][0], ah[sub][1], ah[sub][2], ah[sub][3], ad);
            }
            #pragma unroll
            for (int p = 0; p < 4; p++) {
                uint32_t bd = bbase + so + (uint32_t)(p * 16 * 80 + ks * 32);
                uint32_t m0, m1, m2, m3;
                LDMX4(m0, m1, m2, m3, bd);
                bh[2*p][0] = m0; bh[2*p][1] = m2; bh[2*p+1][0] = m1; bh[2*p+1][1] = m3;
                LDMX4(m0, m1, m2, m3, bd + 20480);
                bl[2*p][0] = m0; bl[2*p][1] = m2; bl[2*p+1][0] = m1; bl[2*p+1][1] = m3;
            }
            #pragma unroll
            for (int sub = 0; sub < 4; sub++)
                #pragma unroll
                for (int nt = 0; nt < 8; nt++) {
                    mma16816(acc[sub][nt], ah[sub], bh[nt]);
                    mma16816(acc[sub][nt], ah[sub], bl[nt]);
                }
        }
        if (c < 15) {
            uint32_t so2 = (uint32_t)((c + 1) & 1) * QSTAGE;
            #pragma unroll
            for (int i = 0; i < 10; i++)
                STS128(dstb[i] + so2, v[i].x, v[i].y, v[i].z, v[i].w);
        }
        __syncthreads();
    }

    #pragma unroll
    for (int sub = 0; sub < 4; sub++) {
        int m  = rb + wm * 64 + sub * 16 + (lid >> 2);
        int m2 = m + 8;
        size_t ro0 = PERM ? (size_t)((m  & 31) * TLEN + (m  >> 5)) : (size_t)m;
        size_t ro1 = PERM ? (size_t)((m2 & 31) * TLEN + (m2 >> 5)) : (size_t)m2;
        #pragma unroll
        for (int nt = 0; nt < 8; nt++) {
            int c0 = cb + wn * 64 + nt * 8 + (lid & 3) * 2;
            float2 bv = *(const float2*)(bias + c0);
            float* a = acc[sub][nt];
            *(float2*)(C + ro0 * (size_t)ldc + c0) = make_float2(a[0] + bv.x, a[1] + bv.y);
            *(float2*)(C + ro1 * (size_t)ldc + c0) = make_float2(a[2] + bv.x, a[3] + bv.y);
        }
    }
}

// ====== helper-block GEMM tile: 64x128, 2-term, 384 threads ==============
__device__ void helper_gemm_tile(uint32_t sb, int rb, int cb,
        const uint16_t* __restrict__ Ah, const uint16_t* __restrict__ Bh,
        const uint16_t* __restrict__ Bl, const float* __restrict__ bias,
        float* __restrict__ C, int tid) {
    int lid = tid & 31, wid = tid >> 5;
    const uint8_t* srcp[4];
    uint32_t dstb[4];
    int valid[4];
    {
        const uint8_t* planes[3] = {(const uint8_t*)Ah, (const uint8_t*)Bh,
                                    (const uint8_t*)Bl};
        const uint32_t poff[3] = {0u, 5120u, 15360u};
        #pragma unroll
        for (int i = 0; i < 4; i++) {
            int s = i * 384 + tid;
            valid[i] = (s < 1280);
            int ss = valid[i] ? s : 0;
            int isB = (ss >= 256);
            int pl  = isB ? (1 + ((ss - 256) >> 9)) : 0;
            int loc = isB ? ((ss - 256) & 511) : ss;
            int row = loc >> 2, col = loc & 3;
            srcp[i] = planes[pl] + (size_t)((pl ? cb : rb) + row) * 1024 + col * 16;
            dstb[i] = sb + poff[pl] + (uint32_t)row * 80 + col * 16;
        }
    }

    uint4 v[4];
    #pragma unroll
    for (int i = 0; i < 4; i++) if (valid[i]) v[i] = *(const uint4*)(srcp[i]);
    #pragma unroll
    for (int i = 0; i < 4; i++)
        if (valid[i]) STS128(dstb[i], v[i].x, v[i].y, v[i].z, v[i].w);
    __syncthreads();

    int wm = wid >> 2, wn = wid & 3;
    uint32_t abase = sb + (uint32_t)(wm * 32 + (lid & 15)) * 80 + (lid >> 4) * 16;
    uint32_t bbase = sb + 5120 + (uint32_t)(wn * 32 + (lid & 15)) * 80 + (lid >> 4) * 16;

    float acc[2][4][4] = {};

    for (int c = 0; c < 16; c++) {
        if (c < 15) {
            #pragma unroll
            for (int i = 0; i < 4; i++)
                if (valid[i]) v[i] = *(const uint4*)(srcp[i] + (c + 1) * 64);
        }
        uint32_t so = (uint32_t)(c & 1) * 25600u;
        if (wid < 8) {
            #pragma unroll
            for (int ks = 0; ks < 2; ks++) {
                uint32_t ah[2][4], bh[4][2], bl[4][2];
                #pragma unroll
                for (int sub = 0; sub < 2; sub++) {
                    uint32_t ad = abase + so + (uint32_t)(sub * 16 * 80 + ks * 32);
                    LDMX4(ah[sub][0], ah[sub][1], ah[sub][2], ah[sub][3], ad);
                }
                #pragma unroll
                for (int p = 0; p < 2; p++) {
                    uint32_t bd = bbase + so + (uint32_t)(p * 16 * 80 + ks * 32);
                    uint32_t m0, m1, m2, m3;
                    LDMX4(m0, m1, m2, m3, bd);
                    bh[2*p][0] = m0; bh[2*p][1] = m2; bh[2*p+1][0] = m1; bh[2*p+1][1] = m3;
                    LDMX4(m0, m1, m2, m3, bd + 10240);
                    bl[2*p][0] = m0; bl[2*p][1] = m2; bl[2*p+1][0] = m1; bl[2*p+1][1] = m3;
                }
                #pragma unroll
                for (int sub = 0; sub < 2; sub++)
                    #pragma unroll
                    for (int nt = 0; nt < 4; nt++) {
                        mma16816(acc[sub][nt], ah[sub], bh[nt]);
                        mma16816(acc[sub][nt], ah[sub], bl[nt]);
                    }
            }
        }
        if (c < 15) {
            uint32_t so2 = (uint32_t)((c + 1) & 1) * 25600u;
            #pragma unroll
            for (int i = 0; i < 4; i++)
                if (valid[i]) STS128(dstb[i] + so2, v[i].x, v[i].y, v[i].z, v[i].w);
        }
        __syncthreads();
    }

    if (wid < 8) {
        #pragma unroll
        for (int sub = 0; sub < 2; sub++) {
            int m  = rb + wm * 32 + sub * 16 + (lid >> 2);
            int m2 = m + 8;
            #pragma unroll
            for (int nt = 0; nt < 4; nt++) {
                int c0 = cb + wn * 32 + nt * 8 + (lid & 3) * 2;
                float2 bv = *(const float2*)(bias + c0);
                float* a = acc[sub][nt];
                *(float2*)(C + (size_t)m  * G4 + c0) = make_float2(a[0] + bv.x, a[1] + bv.y);
                *(float2*)(C + (size_t)m2 * G4 + c0) = make_float2(a[2] + bv.x, a[3] + bv.y);
            }
        }
    }
    __syncthreads();
}

// ================= merged wavefront + helper blocks =================
#define FT      384
#define HROW    80
#define PARTOFF 163840
#define PSTR    36
#define USTR    2304
#define FSMEM   (163840 + 27648)

__device__ __forceinline__ void load_wfrag(const float* wbase, int jA, int jB,
                                           int kq, int kc,
                                           uint32_t ahi[8][4], uint32_t alo[8][4]) {
    #pragma unroll
    for (int kt = 0; kt < 8; kt++) {
        int k0 = kq * 128 + kt * 16 + kc;
        float2 w00 = *(const float2*)(wbase + (size_t)jA * 512 + k0);
        float2 w10 = *(const float2*)(wbase + (size_t)jB * 512 + k0);
        float2 w01 = *(const float2*)(wbase + (size_t)jA * 512 + k0 + 8);
        float2 w11 = *(const float2*)(wbase + (size_t)jB * 512 + k0 + 8);
        cvt2(w00.x, w00.y, ahi[kt][0], alo[kt][0]);
        cvt2(w10.x, w10.y, ahi[kt][1], alo[kt][1]);
        cvt2(w01.x, w01.y, ahi[kt][2], alo[kt][2]);
        cvt2(w11.x, w11.y, ahi[kt][3], alo[kt][3]);
    }
}

__global__ void __launch_bounds__(FT, 1)
k_merged(float* __restrict__ preE, float* __restrict__ preD,
         const float* __restrict__ e0_Whh, const float* __restrict__ e1_Wih,
         const float* __restrict__ e1_Whh, const float* __restrict__ e1_b,
         const float* __restrict__ d0_Whh, const float* __restrict__ d1_Wih,
         const float* __restrict__ d1_Whh, const float* __restrict__ d1_b,
         const float* __restrict__ e0_b, const float* __restrict__ d0_b,
         uint16_t* __restrict__ youth, const float* __restrict__ linW,
         uint16_t* __restrict__ lwh, uint16_t* __restrict__ lwl) {
    extern __shared__ char smc[];
    uint32_t sb = smem_u32(smc);
    int tid = threadIdx.x, bl = blockIdx.x;

    // ================= helper blocks =================
    if (bl >= RB) {
        int hb = bl - RB;
        unsigned L = (*((volatile unsigned*)&g_epoch)) - 1u;
        unsigned L64 = L * 64u;
        if (hb < NGW) {
            // 64 input-GEMM groups in t-order: k<32 enc, k>=32 dec
            for (int k = 0; k < 64; k++) {
                int enc = (k < 32);
                helper_gemm_tile(sb, (k & 31) * 64, hb * 128,
                    enc ? g_xsh : g_xsd,
                    enc ? g_wh : g_wh2, enc ? g_wl : g_wl2,
                    enc ? e0_b : d0_b, enc ? preE : preD, tid);
                if (tid == 0) {
                    __threadfence();
                    unsigned old = atomicAdd(&g_gdone[k], 1u);
                    if ((old & 15u) == 15u) {
                        __threadfence();
                        atomicMax(&g_prog, L64 + (unsigned)k + 1u);
                    }
                }
            }
        }
        // lin_W pack ticket queue (8000 chunks of 2048 elements)
        unsigned lqb = L * 8448u;
        __shared__ unsigned s_tk;
        for (;;) {
            if (tid == 0) s_tk = atomicAdd(&g_lq, 1u);
            __syncthreads();
            unsigned tk = s_tk;
            __syncthreads();
            if (tk < lqb) continue;
            if (tk >= lqb + 8000u) break;
            if (tid < 256) {
                size_t base = ((size_t)(tk - lqb) * 256 + tid) * 8;
                float4 a = *(const float4*)(linW + base);
                float4 c4 = *(const float4*)(linW + base + 4);
                uint32_t h[4], l[4];
                cvt2(a.x, a.y, h[0], l[0]); cvt2(a.z, a.w, h[1], l[1]);
                cvt2(c4.x, c4.y, h[2], l[2]); cvt2(c4.z, c4.w, h[3], l[3]);
                *(uint4*)(lwh + base) = make_uint4(h[0], h[1], h[2], h[3]);
                *(uint4*)(lwl + base) = make_uint4(l[0], l[1], l[2], l[3]);
            }
        }
        return;
    }

    // ================= wavefront blocks =================
    float* part = (float*)(smc + PARTOFF);

    int wid = tid >> 5, l = tid & 31;
    int sec = wid >> 2, kq = wid & 3;

    const float* w_e = (sec == 0) ? e0_Whh : (sec == 1) ? e1_Wih : e1_Whh;
    const float* w_d = (sec == 0) ? d0_Whh : (sec == 1) ? d1_Wih : d1_Whh;
    int wswitch = (sec == 0) ? 64 : 65;

    int rA = l >> 2, rB = rA + 8;
    int jA = (rA >> 2) * 512 + bl * 4 + (rA & 3);
    int jB = (rB >> 2) * 512 + bl * 4 + (rB & 3);
    int kc = (l & 3) * 2;
    uint32_t ahi[8][4], alo[8][4];
    load_wfrag(w_e, jA, jB, kq, kc, ahi, alo);

    int krow = (l & 7) + ((l & 8) ? 8 : 0);
    int ncol = (l & 16) ? 8 : 0;
    uint32_t hbase = sb + ((sec == 2) ? 81920u : 0u)
                   + (uint32_t)(kq * 128 + krow) * HROW + ncol * 2;

    float* myp = part + sec * USTR + kq * 576;

    int stid = tid & 127;
    int m_l = stid >> 5, eb = stid & 31;
    int m_g = bl * 4 + m_l;
    float biasE[4], biasD[4];
    #pragma unroll
    for (int g = 0; g < 4; g++) {
        biasE[g] = e1_b[g * 512 + bl * 4 + m_l];
        biasD[g] = d1_b[g * 512 + bl * 4 + m_l];
    }

    unsigned base = *((volatile unsigned*)&g_flags2[bl * 32]);
    unsigned L64w = (base / 129u) * 64u;

    // entry wait: input-GEMM group 0 (preE step 0/1) must be ready
    if (tid == 0) {
        unsigned tg0 = L64w + 1u;
        for (;;) {
            unsigned gv;
            asm volatile("ld.acquire.gpu.global.u32 %0, [%1];" : "=r"(gv) : "l"(&g_prog));
            if ((int)(gv - tg0) >= 0) break;
        }
    }
    __syncthreads();

    float c0_reg = 0.f, c1_reg = 0.f;

    for (int tau = 0; tau <= 2 * TLEN; tau++) {
        int doL0 = (tau < 2 * TLEN), doL1 = (tau >= 1);

        float pp[4];
        if (sec == 0 && doL0) {
            const float* p = (tau < 64) ? preE : preD;
            int step = (tau < 64) ? tau : tau - 64;
            #pragma unroll
            for (int g = 0; g < 4; g++)
                pp[g] = p[(size_t)(step * 32 + eb) * G4 + g * 512 + bl * 4 + m_l];
        }

        {
            const uint4* s0 = (const uint4*)(&g_hq[0][tau & 1][0][0]);
            const uint4* s1 = (const uint4*)(&g_hq[1][tau & 1][0][0]);
            #pragma unroll
            for (int i = 0; i < 22; i++) {
                int lin = tid + i * FT;
                if (lin < 8192) {
                    uint4 v = __ldcg((lin < 4096 ? s0 : s1) + (lin & 4095));
                    uint32_t ad = sb + (uint32_t)(lin >> 11) * 40960u
                                + (uint32_t)((lin & 2047) >> 2) * HROW
                                + (uint32_t)(lin & 3) * 16u;
                    STS128(ad, v.x, v.y, v.z, v.w);
                }
            }
        }
        __syncthreads();

        int active = (sec == 0) ? doL0 : doL1;
        if (active) {
            float acc[4][4];
            #pragma unroll
            for (int i = 0; i < 4; i++)
                #pragma unroll
                for (int q = 0; q < 4; q++) acc[i][q] = 0.f;
            #pragma unroll
            for (int kt = 0; kt < 8; kt++) {
                uint32_t ka = hbase + (uint32_t)(kt * 16) * HROW;
                uint32_t bh[4][2], bl2[4][2];
                #pragma unroll
                for (int nbp = 0; nbp < 2; nbp++) {
                    uint32_t m0, m1, m2, m3;
                    LDMX4T(m0, m1, m2, m3, ka + nbp * 32);
                    bh[2*nbp][0] = m0; bh[2*nbp][1] = m1;
                    bh[2*nbp+1][0] = m2; bh[2*nbp+1][1] = m3;
                    LDMX4T(m0, m1, m2, m3, ka + nbp * 32 + 40960);
                    bl2[2*nbp][0] = m0; bl2[2*nbp][1] = m1;
                    bl2[2*nbp+1][0] = m2; bl2[2*nbp+1][1] = m3;
                }
                #pragma unroll
                for (int nt = 0; nt < 4; nt++) {
                    mma16816(acc[nt], ahi[kt], bh[nt]);
                    mma16816(acc[nt], ahi[kt], bl2[nt]);
                    mma16816(acc[nt], alo[kt], bh[nt]);
                }
            }
            #pragma unroll
            for (int nt = 0; nt < 4; nt++) {
                int c = nt * 8 + kc;
                *(float2*)(myp + rA * PSTR + c) = make_float2(acc[nt][0], acc[nt][1]);
                *(float2*)(myp + rB * PSTR + c) = make_float2(acc[nt][2], acc[nt][3]);
            }
        }
        __syncthreads();

        if (sec == 0 && doL0) {
            float gv4[4];
            #pragma unroll
            for (int g = 0; g < 4; g++) {
                int o = (g * 4 + m_l) * PSTR + eb;
                gv4[g] = pp[g] + part[o] + part[576 + o] + part[1152 + o] + part[1728 + o];
            }
            c0_reg = fsig(gv4[1]) * c0_reg + fsig(gv4[0]) * ftanh(gv4[2]);
            float h = fsig(gv4[3]) * ftanh(c0_reg);
            float hot = __shfl_xor_sync(0xFFFFFFFFu, h, 1);
            if (!(eb & 1)) {
                uint32_t hi, lo;
                cvt2(h, hot, hi, lo);
                int idx = m_g * 16 + (eb >> 1);
                g_hq[0][(tau + 1) & 1][0][idx] = hi;
                g_hq[0][(tau + 1) & 1][1][idx] = lo;
            }
        }
        float h1v = 0.f;
        if (sec == 1 && doL1) {
            float gv4[4];
            #pragma unroll
            for (int g = 0; g < 4; g++) {
                int o = (g * 4 + m_l) * PSTR + eb;
                float s = (tau >= 65) ? biasD[g] : biasE[g];
                #pragma unroll
                for (int w = 0; w < 4; w++)
                    s += part[USTR + w * 576 + o] + part[2 * USTR + w * 576 + o];
                gv4[g] = s;
            }
            c1_reg = fsig(gv4[1]) * c1_reg + fsig(gv4[0]) * ftanh(gv4[2]);
            h1v = fsig(gv4[3]) * ftanh(c1_reg);
            float hot = __shfl_xor_sync(0xFFFFFFFFu, h1v, 1);
            if (!(eb & 1)) {
                uint32_t hi, lo;
                cvt2(h1v, hot, hi, lo);
                int idx = m_g * 16 + (eb >> 1);
                g_hq[1][(tau - 1) & 1][0][idx] = hi;
                g_hq[1][(tau - 1) & 1][1][idx] = lo;
            }
        }
        __syncthreads();

        if (tid == 0)
            asm volatile("st.release.gpu.global.u32 [%0], %1;"
                :: "l"(g_flags2 + bl * 32), "r"(base + tau + 1) : "memory");
        if (sec == 1 && tau >= 65) {
            uint32_t hw, lw;
            cvt2(h1v, 0.f, hw, lw);
            youth[(size_t)((tau - 65) * 32 + eb) * HD + m_g] = (uint16_t)hw;
        }
        if (tau + 1 == wswitch)
            load_wfrag(w_d, jA, jB, kq, kc, ahi, alo);
        if (tid < 32) {
            unsigned tg = base + tau + 1;
            for (;;) {
                unsigned v0, v1, v2, v3;
                asm volatile("ld.acquire.gpu.global.u32 %0, [%1];" : "=r"(v0)
                    : "l"(g_flags2 + l * 32));
                asm volatile("ld.acquire.gpu.global.u32 %0, [%1];" : "=r"(v1)
                    : "l"(g_flags2 + (l + 32) * 32));
                asm volatile("ld.acquire.gpu.global.u32 %0, [%1];" : "=r"(v2)
                    : "l"(g_flags2 + (l + 64) * 32));
                asm volatile("ld.acquire.gpu.global.u32 %0, [%1];" : "=r"(v3)
                    : "l"(g_flags2 + (l + 96) * 32));
                int ok = ((int)(v0 - tg) >= 0) & ((int)(v1 - tg) >= 0) &
                         ((int)(v2 - tg) >= 0) & ((int)(v3 - tg) >= 0);
                if (__all_sync(0xFFFFFFFFu, ok)) break;
            }
            // input-GEMM readiness for the NEXT round
            if (l == 0 && tau < 2 * TLEN) {
                unsigned nr = (unsigned)(tau + 1);
                unsigned need = (nr < 64u) ? (nr >> 1) + 1u
                                           : 32u + (((nr - 64u) >> 1) + 1u);
                if (need > 64u) need = 64u;
                unsigned tg2 = L64w + need;
                for (;;) {
                    unsigned gv;
                    asm volatile("ld.acquire.gpu.global.u32 %0, [%1];" : "=r"(gv)
                        : "l"(&g_prog));
                    if ((int)(gv - tg2) >= 0) break;
                }
            }
        }
        __syncthreads();
    }
}

// ---------------- launcher ----------------
extern "C" void kernel_launch(void* const* d_in, const int* in_sizes, int n_in,
                              void* d_out, int out_size) {
    const int*   x       = (const int*)  d_in[0];
    const int*   tgt     = (const int*)  d_in[1];
    const float* enc_emb = (const float*)d_in[2];
    const float* dec_emb = (const float*)d_in[3];
    const float* e0_Wih  = (const float*)d_in[4];
    const float* e0_Whh  = (const float*)d_in[5];
    const float* e0_b    = (const float*)d_in[6];
    const float* e1_Wih  = (const float*)d_in[7];
    const float* e1_Whh  = (const float*)d_in[8];
    const float* e1_b    = (const float*)d_in[9];
    const float* d0_Wih  = (const float*)d_in[10];
    const float* d0_Whh  = (const float*)d_in[11];
    const float* d0_b    = (const float*)d_in[12];
    const float* d1_Wih  = (const float*)d_in[13];
    const float* d1_Whh  = (const float*)d_in[14];
    const float* d1_b    = (const float*)d_in[15];
    const float* lin_W   = (const float*)d_in[16];
    const float* lin_b   = (const float*)d_in[17];
    float* out = (float*)d_out;

    float *preE, *preD;
    uint16_t *lwh, *lwl, *u2h;
    cudaGetSymbolAddress((void**)&preE, g_preE);
    cudaGetSymbolAddress((void**)&preD, g_preD);
    cudaGetSymbolAddress((void**)&lwh,  g_lwh);
    cudaGetSymbolAddress((void**)&lwl,  g_lwl);
    cudaGetSymbolAddress((void**)&u2h,  g_u2h);

    cudaFuncSetAttribute(k_merged, cudaFuncAttributeMaxDynamicSharedMemorySize, FSMEM);
    cudaFuncSetAttribute(k_gemm_q<1>, cudaFuncAttributeMaxDynamicSharedMemorySize, QSMEM);

    // fused front: zero + enc/dec embeds + e0/d0 weight packs (+ epoch bump)
    k_front<<<3136, 256>>>(x, tgt, enc_emb, dec_emb, e0_Wih, d0_Wih);

    // wavefront (128 blocks) + helpers (20 blocks: progressive enc/dec input
    // GEMMs with per-group release, then lin_W pack via ticket queue)
    k_merged<<<RB + NHELP, FT, FSMEM>>>(preE, preD,
                                        e0_Whh, e1_Wih, e1_Whh, e1_b,
                                        d0_Whh, d1_Wih, d1_Whh, d1_b,
                                        e0_b, d0_b, u2h, lin_W, lwh, lwl);

    // projection (2-term)
    dim3 gp(16, VOC / 256);
    k_gemm_q<1><<<gp, 256, QSMEM>>>(u2h, lwh, lwl, lin_b, out, VOC);
}

// round 17
// speedup vs baseline: 1.1404x; 1.1404x over previous
#include <cuda_runtime.h>
#include <cuda_bf16.h>
#include <math.h>
#include <stdint.h>

#define BSZ   32
#define TLEN  64
#define ED    512
#define HD    512
#define G4    2048
#define M2    2048
#define VOC   32000
#define RB    128
#define NHELP 20

// ---------------- scratch (device globals; no allocation) ----------------
__device__ float    g_preE[M2 * G4];
__device__ float    g_preD[M2 * G4];
__device__ uint16_t g_xsh[M2 * ED];                     // enc inputs (hi)
__device__ uint16_t g_xsd[M2 * ED];                     // dec inputs (hi)
__device__ uint16_t g_wh [G4 * ED], g_wl [G4 * ED];     // e0_Wih planes
__device__ uint16_t g_wh2[G4 * ED], g_wl2[G4 * ED];     // d0_Wih planes
__device__ uint16_t g_lwh[VOC * ED], g_lwl[VOC * ED];   // lin_W planes
__device__ uint16_t g_u2h[M2 * HD];
__device__ uint32_t g_hq[2][2][2][8192];
__device__ __align__(16) unsigned g_flags2[RB * 32];
__device__ unsigned g_hctr;     // helper completion counter (monotonic)
__device__ unsigned g_ready;    // helper-done epoch (monotonic)

// ================= helpers =================
__device__ __forceinline__ uint32_t smem_u32(const void* p) {
    uint32_t a;
    asm("{ .reg .u64 t; cvta.to.shared.u64 t, %1; cvt.u32.u64 %0, t; }" : "=r"(a) : "l"(p));
    return a;
}
__device__ __forceinline__ float fsig(float x) {
    return __fdividef(1.f, 1.f + __expf(-x));
}
__device__ __forceinline__ float ftanh(float x) {
    return 1.f - __fdividef(2.f, __expf(2.f * x) + 1.f);
}

#define LDMX4(r0, r1, r2, r3, a) \
    asm volatile("ldmatrix.sync.aligned.m8n8.x4.shared.b16 {%0,%1,%2,%3}, [%4];" \
        : "=r"(r0), "=r"(r1), "=r"(r2), "=r"(r3) : "r"(a))

#define LDMX4T(r0, r1, r2, r3, a) \
    asm volatile("ldmatrix.sync.aligned.m8n8.x4.trans.shared.b16 {%0,%1,%2,%3}, [%4];" \
        : "=r"(r0), "=r"(r1), "=r"(r2), "=r"(r3) : "r"(a))

#define STS128(a, r0, r1, r2, r3) \
    asm volatile("st.shared.v4.b32 [%0], {%1,%2,%3,%4};" \
        :: "r"(a), "r"(r0), "r"(r1), "r"(r2), "r"(r3) : "memory")

__device__ __forceinline__ void mma16816(float* d, const uint32_t* a, const uint32_t* b) {
    asm volatile("mma.sync.aligned.m16n8k16.row.col.f32.bf16.bf16.f32 "
        "{%0,%1,%2,%3},{%4,%5,%6,%7},{%8,%9},{%0,%1,%2,%3};"
        : "+f"(d[0]), "+f"(d[1]), "+f"(d[2]), "+f"(d[3])
        : "r"(a[0]), "r"(a[1]), "r"(a[2]), "r"(a[3]), "r"(b[0]), "r"(b[1]));
}

__device__ __forceinline__ void cvt2(float x, float y, uint32_t& hi, uint32_t& lo) {
    asm("cvt.rn.bf16x2.f32 %0, %1, %2;" : "=r"(hi) : "f"(y), "f"(x));
    float rx = x - __uint_as_float(hi << 16);
    float ry = y - __uint_as_float(hi & 0xFFFF0000u);
    asm("cvt.rn.bf16x2.f32 %0, %1, %2;" : "=r"(lo) : "f"(ry), "f"(rx));
}

// ================= fused front kernel (R16, verified 7.8us) =================
// blocks [0,64): zero g_hq; [64,1088): enc embed; [1088,2112): dec embed;
// [2112,2624): pack e0_Wih; [2624,3136): pack d0_Wih.
__global__ void k_front(const int* __restrict__ x, const int* __restrict__ tgt,
                        const float* __restrict__ enc_emb,
                        const float* __restrict__ dec_emb,
                        const float* __restrict__ e0_Wih,
                        const float* __restrict__ d0_Wih) {
    int b = blockIdx.x, tid = threadIdx.x;
    if (b < 64) {
        ((uint4*)g_hq)[b * 256 + tid] = make_uint4(0u, 0u, 0u, 0u);
    } else if (b < 2112) {
        int dec = (b >= 1088);
        int row = ((dec ? b - 1088 : b - 64) << 1) + (tid >> 7);
        int t = row >> 5, bb = row & 31;
        int tok = dec ? ((t == 0) ? 1 : tgt[bb * TLEN + t - 1]) : x[bb * TLEN + t];
        const float* emb = dec ? dec_emb : enc_emb;
        int c = tid & 127;
        float4 f = ((const float4*)(emb + (size_t)tok * ED))[c];
        uint32_t h0, l0, h1, l1;
        cvt2(f.x, f.y, h0, l0);
        cvt2(f.z, f.w, h1, l1);
        uint16_t* dst = dec ? g_xsd : g_xsh;
        *(uint2*)(dst + (size_t)row * ED + c * 4) = make_uint2(h0, h1);
    } else {
        int dec = (b >= 2624);
        size_t base = ((size_t)(dec ? b - 2624 : b - 2112) * 256 + tid) * 8;
        const float* src = dec ? d0_Wih : e0_Wih;
        uint16_t* hi = dec ? g_wh2 : g_wh;
        uint16_t* lo = dec ? g_wl2 : g_wl;
        float4 a = *(const float4*)(src + base);
        float4 c4 = *(const float4*)(src + base + 4);
        uint32_t h[4], l[4];
        cvt2(a.x, a.y, h[0], l[0]); cvt2(a.z, a.w, h[1], l[1]);
        cvt2(c4.x, c4.y, h[2], l[2]); cvt2(c4.z, c4.w, h[3], l[3]);
        *(uint4*)(hi + base) = make_uint4(h[0], h[1], h[2], h[3]);
        *(uint4*)(lo + base) = make_uint4(l[0], l[1], l[2], l[3]);
    }
}

// ====== 2-term split-bf16 HMMA GEMM: 128x256 tile (enc in-GEMM + proj) ====
#define QSTAGE 51200
#define QSMEM  102400

template<int PERM>
__global__ void __launch_bounds__(256, 1)
k_gemm_q(const uint16_t* __restrict__ Ah,
         const uint16_t* __restrict__ Bh, const uint16_t* __restrict__ Bl,
         const float* __restrict__ bias, float* __restrict__ C, int ldc) {
    extern __shared__ char smx[];
    uint32_t sb = smem_u32(smx);
    int tid = threadIdx.x, lid = tid & 31, wid = tid >> 5;
    int wm = wid >> 2, wn = wid & 3;
    int rb = blockIdx.x * 128, cb = blockIdx.y * 256;

    const uint8_t* srcp[10];
    uint32_t dstb[10];
    {
        const uint8_t* planes[3] = {(const uint8_t*)Ah, (const uint8_t*)Bh,
                                    (const uint8_t*)Bl};
        const uint32_t poff[3] = {0u, 10240u, 30720u};
        #pragma unroll
        for (int i = 0; i < 10; i++) {
            int s = i * 256 + tid;
            int isB = (s >= 512);
            int pl  = isB ? (1 + ((s - 512) >> 10)) : 0;
            int loc = isB ? ((s - 512) & 1023) : s;
            int row = loc >> 2, col = loc & 3;
            srcp[i] = planes[pl] + (size_t)((pl ? cb : rb) + row) * 1024 + col * 16;
            dstb[i] = sb + poff[pl] + (uint32_t)row * 80 + col * 16;
        }
    }

    uint4 v[10];
    #pragma unroll
    for (int i = 0; i < 10; i++) v[i] = *(const uint4*)(srcp[i]);
    #pragma unroll
    for (int i = 0; i < 10; i++) STS128(dstb[i], v[i].x, v[i].y, v[i].z, v[i].w);
    __syncthreads();

    uint32_t abase = sb + (uint32_t)(wm * 64 + (lid & 15)) * 80 + (lid >> 4) * 16;
    uint32_t bbase = sb + 10240 + (uint32_t)(wn * 64 + (lid & 15)) * 80 + (lid >> 4) * 16;

    float acc[4][8][4] = {};

    for (int c = 0; c < 16; c++) {
        if (c < 15) {
            #pragma unroll
            for (int i = 0; i < 10; i++) v[i] = *(const uint4*)(srcp[i] + (c + 1) * 64);
        }
        uint32_t so = (uint32_t)(c & 1) * QSTAGE;
        #pragma unroll
        for (int ks = 0; ks < 2; ks++) {
            uint32_t ah[4][4], bh[8][2], bl[8][2];
            #pragma unroll
            for (int sub = 0; sub < 4; sub++) {
                uint32_t ad = abase + so + (uint32_t)(sub * 16 * 80 + ks * 32);
                LDMX4(ah[sub][0], ah[sub][1], ah[sub][2], ah[sub][3], ad);
            }
            #pragma unroll
            for (int p = 0; p < 4; p++) {
                uint32_t bd = bbase + so + (uint32_t)(p * 16 * 80 + ks * 32);
                uint32_t m0, m1, m2, m3;
                LDMX4(m0, m1, m2, m3, bd);
                bh[2*p][0] = m0; bh[2*p][1] = m2; bh[2*p+1][0] = m1; bh[2*p+1][1] = m3;
                LDMX4(m0, m1, m2, m3, bd + 20480);
                bl[2*p][0] = m0; bl[2*p][1] = m2; bl[2*p+1][0] = m1; bl[2*p+1][1] = m3;
            }
            #pragma unroll
            for (int sub = 0; sub < 4; sub++)
                #pragma unroll
                for (int nt = 0; nt < 8; nt++) {
                    mma16816(acc[sub][nt], ah[sub], bh[nt]);
                    mma16816(acc[sub][nt], ah[sub], bl[nt]);
                }
        }
        if (c < 15) {
            uint32_t so2 = (uint32_t)((c + 1) & 1) * QSTAGE;
            #pragma unroll
            for (int i = 0; i < 10; i++)
                STS128(dstb[i] + so2, v[i].x, v[i].y, v[i].z, v[i].w);
        }
        __syncthreads();
    }

    #pragma unroll
    for (int sub = 0; sub < 4; sub++) {
        int m  = rb + wm * 64 + sub * 16 + (lid >> 2);
        int m2 = m + 8;
        size_t ro0 = PERM ? (size_t)((m  & 31) * TLEN + (m  >> 5)) : (size_t)m;
        size_t ro1 = PERM ? (size_t)((m2 & 31) * TLEN + (m2 >> 5)) : (size_t)m2;
        #pragma unroll
        for (int nt = 0; nt < 8; nt++) {
            int c0 = cb + wn * 64 + nt * 8 + (lid & 3) * 2;
            float2 bv = *(const float2*)(bias + c0);
            float* a = acc[sub][nt];
            *(float2*)(C + ro0 * (size_t)ldc + c0) = make_float2(a[0] + bv.x, a[1] + bv.y);
            *(float2*)(C + ro1 * (size_t)ldc + c0) = make_float2(a[2] + bv.x, a[3] + bv.y);
        }
    }
}

// ====== helper-block GEMM tile: 64x128, 2-term, 384 threads (R15) =========
__device__ void helper_gemm_tile(uint32_t sb, int rb, int cb,
        const uint16_t* __restrict__ Ah, const uint16_t* __restrict__ Bh,
        const uint16_t* __restrict__ Bl, const float* __restrict__ bias,
        float* __restrict__ C, int tid) {
    int lid = tid & 31, wid = tid >> 5;
    const uint8_t* srcp[4];
    uint32_t dstb[4];
    int valid[4];
    {
        const uint8_t* planes[3] = {(const uint8_t*)Ah, (const uint8_t*)Bh,
                                    (const uint8_t*)Bl};
        const uint32_t poff[3] = {0u, 5120u, 15360u};
        #pragma unroll
        for (int i = 0; i < 4; i++) {
            int s = i * 384 + tid;
            valid[i] = (s < 1280);
            int ss = valid[i] ? s : 0;
            int isB = (ss >= 256);
            int pl  = isB ? (1 + ((ss - 256) >> 9)) : 0;
            int loc = isB ? ((ss - 256) & 511) : ss;
            int row = loc >> 2, col = loc & 3;
            srcp[i] = planes[pl] + (size_t)((pl ? cb : rb) + row) * 1024 + col * 16;
            dstb[i] = sb + poff[pl] + (uint32_t)row * 80 + col * 16;
        }
    }

    uint4 v[4];
    #pragma unroll
    for (int i = 0; i < 4; i++) if (valid[i]) v[i] = *(const uint4*)(srcp[i]);
    #pragma unroll
    for (int i = 0; i < 4; i++)
        if (valid[i]) STS128(dstb[i], v[i].x, v[i].y, v[i].z, v[i].w);
    __syncthreads();

    int wm = wid >> 2, wn = wid & 3;
    uint32_t abase = sb + (uint32_t)(wm * 32 + (lid & 15)) * 80 + (lid >> 4) * 16;
    uint32_t bbase = sb + 5120 + (uint32_t)(wn * 32 + (lid & 15)) * 80 + (lid >> 4) * 16;

    float acc[2][4][4] = {};

    for (int c = 0; c < 16; c++) {
        if (c < 15) {
            #pragma unroll
            for (int i = 0; i < 4; i++)
                if (valid[i]) v[i] = *(const uint4*)(srcp[i] + (c + 1) * 64);
        }
        uint32_t so = (uint32_t)(c & 1) * 25600u;
        if (wid < 8) {
            #pragma unroll
            for (int ks = 0; ks < 2; ks++) {
                uint32_t ah[2][4], bh[4][2], bl[4][2];
                #pragma unroll
                for (int sub = 0; sub < 2; sub++) {
                    uint32_t ad = abase + so + (uint32_t)(sub * 16 * 80 + ks * 32);
                    LDMX4(ah[sub][0], ah[sub][1], ah[sub][2], ah[sub][3], ad);
                }
                #pragma unroll
                for (int p = 0; p < 2; p++) {
                    uint32_t bd = bbase + so + (uint32_t)(p * 16 * 80 + ks * 32);
                    uint32_t m0, m1, m2, m3;
                    LDMX4(m0, m1, m2, m3, bd);
                    bh[2*p][0] = m0; bh[2*p][1] = m2; bh[2*p+1][0] = m1; bh[2*p+1][1] = m3;
                    LDMX4(m0, m1, m2, m3, bd + 10240);
                    bl[2*p][0] = m0; bl[2*p][1] = m2; bl[2*p+1][0] = m1; bl[2*p+1][1] = m3;
                }
                #pragma unroll
                for (int sub = 0; sub < 2; sub++)
                    #pragma unroll
                    for (int nt = 0; nt < 4; nt++) {
                        mma16816(acc[sub][nt], ah[sub], bh[nt]);
                        mma16816(acc[sub][nt], ah[sub], bl[nt]);
                    }
            }
        }
        if (c < 15) {
            uint32_t so2 = (uint32_t)((c + 1) & 1) * 25600u;
            #pragma unroll
            for (int i = 0; i < 4; i++)
                if (valid[i]) STS128(dstb[i] + so2, v[i].x, v[i].y, v[i].z, v[i].w);
        }
        __syncthreads();
    }

    if (wid < 8) {
        #pragma unroll
        for (int sub = 0; sub < 2; sub++) {
            int m  = rb + wm * 32 + sub * 16 + (lid >> 2);
            int m2 = m + 8;
            #pragma unroll
            for (int nt = 0; nt < 4; nt++) {
                int c0 = cb + wn * 32 + nt * 8 + (lid & 3) * 2;
                float2 bv = *(const float2*)(bias + c0);
                float* a = acc[sub][nt];
                *(float2*)(C + (size_t)m  * G4 + c0) = make_float2(a[0] + bv.x, a[1] + bv.y);
                *(float2*)(C + (size_t)m2 * G4 + c0) = make_float2(a[2] + bv.x, a[3] + bv.y);
            }
        }
    }
    __syncthreads();
}

// ================= merged wavefront + helper blocks (R15) ==================
#define FT      384
#define HROW    80
#define PARTOFF 163840
#define PSTR    36
#define USTR    2304
#define FSMEM   (163840 + 27648)

__device__ __forceinline__ void load_wfrag(const float* wbase, int jA, int jB,
                                           int kq, int kc,
                                           uint32_t ahi[8][4], uint32_t alo[8][4]) {
    #pragma unroll
    for (int kt = 0; kt < 8; kt++) {
        int k0 = kq * 128 + kt * 16 + kc;
        float2 w00 = *(const float2*)(wbase + (size_t)jA * 512 + k0);
        float2 w10 = *(const float2*)(wbase + (size_t)jB * 512 + k0);
        float2 w01 = *(const float2*)(wbase + (size_t)jA * 512 + k0 + 8);
        float2 w11 = *(const float2*)(wbase + (size_t)jB * 512 + k0 + 8);
        cvt2(w00.x, w00.y, ahi[kt][0], alo[kt][0]);
        cvt2(w10.x, w10.y, ahi[kt][1], alo[kt][1]);
        cvt2(w01.x, w01.y, ahi[kt][2], alo[kt][2]);
        cvt2(w11.x, w11.y, ahi[kt][3], alo[kt][3]);
    }
}

__global__ void __launch_bounds__(FT, 1)
k_merged(float* __restrict__ preD, const float* __restrict__ preE,
         const float* __restrict__ e0_Whh, const float* __restrict__ e1_Wih,
         const float* __restrict__ e1_Whh, const float* __restrict__ e1_b,
         const float* __restrict__ d0_Whh, const float* __restrict__ d1_Wih,
         const float* __restrict__ d1_Whh, const float* __restrict__ d1_b,
         uint16_t* __restrict__ youth,
         const uint16_t* __restrict__ hxs, const uint16_t* __restrict__ hwh,
         const uint16_t* __restrict__ hwl, const float* __restrict__ hbias,
         const float* __restrict__ linW,
         uint16_t* __restrict__ lwh, uint16_t* __restrict__ lwl) {
    extern __shared__ char smc[];
    uint32_t sb = smem_u32(smc);
    int tid = threadIdx.x, bl = blockIdx.x;

    // ================= helper blocks: dec in-GEMM + lin_W pack =============
    if (bl >= RB) {
        int hb = bl - RB;
        for (int t = hb; t < 512; t += NHELP) {
            int rb2 = (t & 31) * 64, cb2 = (t >> 5) * 128;
            helper_gemm_tile(sb, rb2, cb2, hxs, hwh, hwl, hbias, preD, tid);
        }
        __threadfence();
        __syncthreads();
        if (tid == 0) {
            unsigned old = atomicAdd(&g_hctr, 1u);
            if ((old % NHELP) == (NHELP - 1u))
                asm volatile("st.release.gpu.global.u32 [%0], %1;"
                    :: "l"(&g_ready), "r"(old / NHELP + 1u) : "memory");
        }
        // lin_W pack (needed only by the projection kernel, after this one)
        for (size_t i = (size_t)hb * FT + tid; i < (size_t)(VOC * ED) / 8;
             i += (size_t)NHELP * FT) {
            size_t basei = i * 8;
            float4 a = *(const float4*)(linW + basei);
            float4 b2 = *(const float4*)(linW + basei + 4);
            uint32_t h[4], l[4];
            cvt2(a.x, a.y, h[0], l[0]); cvt2(a.z, a.w, h[1], l[1]);
            cvt2(b2.x, b2.y, h[2], l[2]); cvt2(b2.z, b2.w, h[3], l[3]);
            *(uint4*)(lwh + basei) = make_uint4(h[0], h[1], h[2], h[3]);
            *(uint4*)(lwl + basei) = make_uint4(l[0], l[1], l[2], l[3]);
        }
        return;
    }

    // ================= wavefront blocks (unchanged math) ===================
    float* part = (float*)(smc + PARTOFF);

    int wid = tid >> 5, l = tid & 31;
    int sec = wid >> 2, kq = wid & 3;

    const float* w_e = (sec == 0) ? e0_Whh : (sec == 1) ? e1_Wih : e1_Whh;
    const float* w_d = (sec == 0) ? d0_Whh : (sec == 1) ? d1_Wih : d1_Whh;
    int wswitch = (sec == 0) ? 64 : 65;

    int rA = l >> 2, rB = rA + 8;
    int jA = (rA >> 2) * 512 + bl * 4 + (rA & 3);
    int jB = (rB >> 2) * 512 + bl * 4 + (rB & 3);
    int kc = (l & 3) * 2;
    uint32_t ahi[8][4], alo[8][4];
    load_wfrag(w_e, jA, jB, kq, kc, ahi, alo);

    int krow = (l & 7) + ((l & 8) ? 8 : 0);
    int ncol = (l & 16) ? 8 : 0;
    uint32_t hbase = sb + ((sec == 2) ? 81920u : 0u)
                   + (uint32_t)(kq * 128 + krow) * HROW + ncol * 2;

    float* myp = part + sec * USTR + kq * 576;

    int stid = tid & 127;
    int m_l = stid >> 5, eb = stid & 31;
    int m_g = bl * 4 + m_l;
    float biasE[4], biasD[4];
    #pragma unroll
    for (int g = 0; g < 4; g++) {
        biasE[g] = e1_b[g * 512 + bl * 4 + m_l];
        biasD[g] = d1_b[g * 512 + bl * 4 + m_l];
    }

    unsigned base = *((volatile unsigned*)&g_flags2[bl * 32]);

    float c0_reg = 0.f, c1_reg = 0.f;

    for (int tau = 0; tau <= 2 * TLEN; tau++) {
        int doL0 = (tau < 2 * TLEN), doL1 = (tau >= 1);

        float pp[4];
        if (sec == 0 && doL0) {
            const float* p = (tau < 64) ? preE : preD;
            int step = (tau < 64) ? tau : tau - 64;
            #pragma unroll
            for (int g = 0; g < 4; g++)
                pp[g] = p[(size_t)(step * 32 + eb) * G4 + g * 512 + bl * 4 + m_l];
        }

        {
            const uint4* s0 = (const uint4*)(&g_hq[0][tau & 1][0][0]);
            const uint4* s1 = (const uint4*)(&g_hq[1][tau & 1][0][0]);
            #pragma unroll
            for (int i = 0; i < 22; i++) {
                int lin = tid + i * FT;
                if (lin < 8192) {
                    uint4 v = __ldcg((lin < 4096 ? s0 : s1) + (lin & 4095));
                    uint32_t ad = sb + (uint32_t)(lin >> 11) * 40960u
                                + (uint32_t)((lin & 2047) >> 2) * HROW
                                + (uint32_t)(lin & 3) * 16u;
                    STS128(ad, v.x, v.y, v.z, v.w);
                }
            }
        }
        __syncthreads();

        int active = (sec == 0) ? doL0 : doL1;
        if (active) {
            float acc[4][4];
            #pragma unroll
            for (int i = 0; i < 4; i++)
                #pragma unroll
                for (int q = 0; q < 4; q++) acc[i][q] = 0.f;
            #pragma unroll
            for (int kt = 0; kt < 8; kt++) {
                uint32_t ka = hbase + (uint32_t)(kt * 16) * HROW;
                uint32_t bh[4][2], bl2[4][2];
                #pragma unroll
                for (int nbp = 0; nbp < 2; nbp++) {
                    uint32_t m0, m1, m2, m3;
                    LDMX4T(m0, m1, m2, m3, ka + nbp * 32);
                    bh[2*nbp][0] = m0; bh[2*nbp][1] = m1;
                    bh[2*nbp+1][0] = m2; bh[2*nbp+1][1] = m3;
                    LDMX4T(m0, m1, m2, m3, ka + nbp * 32 + 40960);
                    bl2[2*nbp][0] = m0; bl2[2*nbp][1] = m1;
                    bl2[2*nbp+1][0] = m2; bl2[2*nbp+1][1] = m3;
                }
                #pragma unroll
                for (int nt = 0; nt < 4; nt++) {
                    mma16816(acc[nt], ahi[kt], bh[nt]);
                    mma16816(acc[nt], ahi[kt], bl2[nt]);
                    mma16816(acc[nt], alo[kt], bh[nt]);
                }
            }
            #pragma unroll
            for (int nt = 0; nt < 4; nt++) {
                int c = nt * 8 + kc;
                *(float2*)(myp + rA * PSTR + c) = make_float2(acc[nt][0], acc[nt][1]);
                *(float2*)(myp + rB * PSTR + c) = make_float2(acc[nt][2], acc[nt][3]);
            }
        }
        __syncthreads();

        if (sec == 0 && doL0) {
            float gv4[4];
            #pragma unroll
            for (int g = 0; g < 4; g++) {
                int o = (g * 4 + m_l) * PSTR + eb;
                gv4[g] = pp[g] + part[o] + part[576 + o] + part[1152 + o] + part[1728 + o];
            }
            c0_reg = fsig(gv4[1]) * c0_reg + fsig(gv4[0]) * ftanh(gv4[2]);
            float h = fsig(gv4[3]) * ftanh(c0_reg);
            float hot = __shfl_xor_sync(0xFFFFFFFFu, h, 1);
            if (!(eb & 1)) {
                uint32_t hi, lo;
                cvt2(h, hot, hi, lo);
                int idx = m_g * 16 + (eb >> 1);
                g_hq[0][(tau + 1) & 1][0][idx] = hi;
                g_hq[0][(tau + 1) & 1][1][idx] = lo;
            }
        }
        float h1v = 0.f;
        if (sec == 1 && doL1) {
            float gv4[4];
            #pragma unroll
            for (int g = 0; g < 4; g++) {
                int o = (g * 4 + m_l) * PSTR + eb;
                float s = (tau >= 65) ? biasD[g] : biasE[g];
                #pragma unroll
                for (int w = 0; w < 4; w++)
                    s += part[USTR + w * 576 + o] + part[2 * USTR + w * 576 + o];
                gv4[g] = s;
            }
            c1_reg = fsig(gv4[1]) * c1_reg + fsig(gv4[0]) * ftanh(gv4[2]);
            h1v = fsig(gv4[3]) * ftanh(c1_reg);
            float hot = __shfl_xor_sync(0xFFFFFFFFu, h1v, 1);
            if (!(eb & 1)) {
                uint32_t hi, lo;
                cvt2(h1v, hot, hi, lo);
                int idx = m_g * 16 + (eb >> 1);
                g_hq[1][(tau - 1) & 1][0][idx] = hi;
                g_hq[1][(tau - 1) & 1][1][idx] = lo;
            }
        }
        __syncthreads();

        if (tid == 0)
            asm volatile("st.release.gpu.global.u32 [%0], %1;"
                :: "l"(g_flags2 + bl * 32), "r"(base + tau + 1) : "memory");
        if (sec == 1 && tau >= 65) {
            uint32_t hw, lw;
            cvt2(h1v, 0.f, hw, lw);
            youth[(size_t)((tau - 65) * 32 + eb) * HD + m_g] = (uint16_t)hw;
        }
        if (tau + 1 == wswitch)
            load_wfrag(w_d, jA, jB, kq, kc, ahi, alo);
        if (tid < 32) {
            unsigned tg = base + tau + 1;
            for (;;) {
                unsigned v0, v1, v2, v3;
                asm volatile("ld.acquire.gpu.global.u32 %0, [%1];" : "=r"(v0)
                    : "l"(g_flags2 + l * 32));
                asm volatile("ld.acquire.gpu.global.u32 %0, [%1];" : "=r"(v1)
                    : "l"(g_flags2 + (l + 32) * 32));
                asm volatile("ld.acquire.gpu.global.u32 %0, [%1];" : "=r"(v2)
                    : "l"(g_flags2 + (l + 64) * 32));
                asm volatile("ld.acquire.gpu.global.u32 %0, [%1];" : "=r"(v3)
                    : "l"(g_flags2 + (l + 96) * 32));
                int ok = ((int)(v0 - tg) >= 0) & ((int)(v1 - tg) >= 0) &
                         ((int)(v2 - tg) >= 0) & ((int)(v3 - tg) >= 0);
                if (__all_sync(0xFFFFFFFFu, ok)) break;
            }
            // before entering decoder phase: wait for helper blocks (preD ready)
            if (tau == 63) {
                unsigned gtar = base / 129u + 1u;
                for (;;) {
                    unsigned gv;
                    asm volatile("ld.acquire.gpu.global.u32 %0, [%1];" : "=r"(gv)
                        : "l"(&g_ready));
                    if ((int)(gv - gtar) >= 0) break;
                }
            }
        }
        __syncthreads();
    }
}

// ---------------- launcher ----------------
extern "C" void kernel_launch(void* const* d_in, const int* in_sizes, int n_in,
                              void* d_out, int out_size) {
    const int*   x       = (const int*)  d_in[0];
    const int*   tgt     = (const int*)  d_in[1];
    const float* enc_emb = (const float*)d_in[2];
    const float* dec_emb = (const float*)d_in[3];
    const float* e0_Wih  = (const float*)d_in[4];
    const float* e0_Whh  = (const float*)d_in[5];
    const float* e0_b    = (const float*)d_in[6];
    const float* e1_Wih  = (const float*)d_in[7];
    const float* e1_Whh  = (const float*)d_in[8];
    const float* e1_b    = (const float*)d_in[9];
    const float* d0_Wih  = (const float*)d_in[10];
    const float* d0_Whh  = (const float*)d_in[11];
    const float* d0_b    = (const float*)d_in[12];
    const float* d1_Wih  = (const float*)d_in[13];
    const float* d1_Whh  = (const float*)d_in[14];
    const float* d1_b    = (const float*)d_in[15];
    const float* lin_W   = (const float*)d_in[16];
    const float* lin_b   = (const float*)d_in[17];
    float* out = (float*)d_out;

    float *preE, *preD;
    uint16_t *xsh, *xsd, *wh, *wl, *wh2, *wl2, *lwh, *lwl, *u2h;
    cudaGetSymbolAddress((void**)&preE, g_preE);
    cudaGetSymbolAddress((void**)&preD, g_preD);
    cudaGetSymbolAddress((void**)&xsh,  g_xsh);
    cudaGetSymbolAddress((void**)&xsd,  g_xsd);
    cudaGetSymbolAddress((void**)&wh,   g_wh);
    cudaGetSymbolAddress((void**)&wl,   g_wl);
    cudaGetSymbolAddress((void**)&wh2,  g_wh2);
    cudaGetSymbolAddress((void**)&wl2,  g_wl2);
    cudaGetSymbolAddress((void**)&lwh,  g_lwh);
    cudaGetSymbolAddress((void**)&lwl,  g_lwl);
    cudaGetSymbolAddress((void**)&u2h,  g_u2h);

    cudaFuncSetAttribute(k_merged, cudaFuncAttributeMaxDynamicSharedMemorySize, FSMEM);
    cudaFuncSetAttribute(k_gemm_q<0>, cudaFuncAttributeMaxDynamicSharedMemorySize, QSMEM);
    cudaFuncSetAttribute(k_gemm_q<1>, cudaFuncAttributeMaxDynamicSharedMemorySize, QSMEM);

    // fused front: zero + enc/dec embeds + e0/d0 weight packs (one launch)
    k_front<<<3136, 256>>>(x, tgt, enc_emb, dec_emb, e0_Wih, d0_Wih);

    // encoder in-GEMM (critical path)
    dim3 gg(16, 8);
    k_gemm_q<0><<<gg, 256, QSMEM>>>(xsh, wh, wl, e0_b, preE, G4);

    // wavefront (128 blocks) + helpers (20 blocks: dec in-GEMM, lin_W pack)
    k_merged<<<RB + NHELP, FT, FSMEM>>>(preD, preE,
                                        e0_Whh, e1_Wih, e1_Whh, e1_b,
                                        d0_Whh, d1_Wih, d1_Whh, d1_b, u2h,
                                        xsd, wh2, wl2, d0_b, lin_W, lwh, lwl);

    // projection (2-term)
    dim3 gp(16, VOC / 256);
    k_gemm_q<1><<<gp, 256, QSMEM>>>(u2h, lwh, lwl, lin_b, out, VOC);
}